// round 11
// baseline (speedup 1.0000x reference)
#include <cuda_runtime.h>
#include <cuda_bf16.h>
#include <cstdint>

#define NPTS    16384
#define THREADS 256
#define QPT     16                      // queries per thread (8 packed f32x2 pairs)
#define QPB     (THREADS * QPT)         // 4096 queries per block
#define QC      (NPTS / QPB)            // 4 query chunks
#define TSLICES 74                      // 4 * 74 = 296 blocks = 2 per SM
#define TS_MAX  222                     // ceil(16384 / 74)
#define TS_PAD  224                     // 7 groups of 32

// ---- device scratch (no allocations allowed) ----
__device__ unsigned g_minrowU[NPTS];    // float bits, clamped >=0, exact-min
__device__ unsigned g_mincolU[NPTS];
__device__ float    g_partial[128];
__device__ unsigned g_count = 0;

#define FMA2(d, a, b, c) \
    asm("fma.rn.f32x2 %0, %1, %2, %3;" : "=l"(d) : "l"(a), "l"(b), "l"(c))
#define ADD2(d, a, b) \
    asm("add.rn.f32x2 %0, %1, %2;" : "=l"(d) : "l"(a), "l"(b))
#define PACK2(d, lo, hi) \
    asm("mov.b64 %0, {%1, %2};" : "=l"(d) : "f"(lo), "f"(hi))
#define UNPK2(lo, hi, s) \
    asm("mov.b64 {%0, %1}, %2;" : "=f"(lo), "=f"(hi) : "l"(s))

// ---------------------------------------------------------------------------
__global__ void chamfer_init_kernel() {
    int i = blockIdx.x * blockDim.x + threadIdx.x;
    if (i < NPTS) { g_minrowU[i] = 0x7F800000u; g_mincolU[i] = 0x7F800000u; }
}

// ---------------------------------------------------------------------------
// Fused single-pass, rotation scheme, 2 CTAs/SM.
// v = a*x + b*y + c*z + |t|^2 (w_q deferred for rows; added only for cols).
// Row mins: registers; col mins: per-warp smem; outputs via exact atomicMin.
// ---------------------------------------------------------------------------
__global__ __launch_bounds__(THREADS, 2) void chamfer_fused_kernel(
        const float* __restrict__ Xc, const float* __restrict__ Xt) {
    __shared__ float4 sA[TS_PAD];            // {x, x, y, y}
    __shared__ float4 sB[TS_PAD];            // {z, z, w, w}  (w = |t|^2)
    __shared__ float  scolw[8][TS_PAD];      // per-warp col-min accumulators

    const int bid = blockIdx.x;
    const int qc  = bid / TSLICES;           // 0..3
    const int ts  = bid % TSLICES;           // 0..73
    const int qbase = qc * QPB;
    const int t0  = ts * TS_MAX;
    const int nt  = min(TS_MAX, NPTS - t0);
    const int tid = threadIdx.x;
    const int wid = tid >> 5;
    const int lane = tid & 31;

    // ---- stage targets (sentinel-pad) + init col accumulators ----
    if (tid < TS_PAD) {
        float x = 0.0f, y = 0.0f, z = 0.0f, w = 1e30f;
        if (tid < nt) {
            int gi = t0 + tid;
            x = Xt[3 * gi + 0]; y = Xt[3 * gi + 1]; z = Xt[3 * gi + 2];
            w = fmaf(x, x, fmaf(y, y, z * z));
        }
        sA[tid] = make_float4(x, x, y, y);
        sB[tid] = make_float4(z, z, w, w);
    }
    #pragma unroll
    for (int k = 0; k < (8 * TS_PAD) / THREADS; k++)
        (&scolw[0][0])[tid + k * THREADS] = 3.4e38f;

    // ---- 16 queries per thread -> 8 packed coefficient quads ----
    unsigned long long aa[8], bb[8], cc[8], ww[8];
    #pragma unroll
    for (int p = 0; p < 8; p++) {
        int qe = qbase + (2 * p) * THREADS + tid;
        int qo = qe + THREADS;
        float xe = Xc[3 * qe], ye = Xc[3 * qe + 1], ze = Xc[3 * qe + 2];
        float xo = Xc[3 * qo], yo = Xc[3 * qo + 1], zo = Xc[3 * qo + 2];
        PACK2(aa[p], -2.0f * xe, -2.0f * xo);
        PACK2(bb[p], -2.0f * ye, -2.0f * yo);
        PACK2(cc[p], -2.0f * ze, -2.0f * zo);
        PACK2(ww[p], fmaf(xe, xe, fmaf(ye, ye, ze * ze)),
                     fmaf(xo, xo, fmaf(yo, yo, zo * zo)));
    }

    float mn[16];
    #pragma unroll
    for (int q = 0; q < 16; q++) mn[q] = 3.4e38f;

    __syncthreads();

    // ---- main loop: 7 groups of 32 targets, rotated across lanes ----
    for (int g = 0; g < TS_PAD; g += 32) {
        int idx = g + lane;
        #pragma unroll 4
        for (int t = 0; t < 32; t++) {
            const ulonglong2 A = *reinterpret_cast<const ulonglong2*>(&sA[idx]);
            const ulonglong2 B = *reinterpret_cast<const ulonglong2*>(&sB[idx]);
            float c = 3.4e38f;
            #pragma unroll
            for (int p = 0; p < 8; p++) {
                unsigned long long v, u;
                float vl, vh, ul, uh;
                FMA2(v, cc[p], B.x, B.y);    // c*z + |t|^2
                FMA2(v, bb[p], A.y, v);      // + b*y
                FMA2(v, aa[p], A.x, v);      // + a*x   (w_q deferred)
                UNPK2(vl, vh, v);
                mn[2 * p]     = fminf(mn[2 * p],     vl);
                mn[2 * p + 1] = fminf(mn[2 * p + 1], vh);
                ADD2(u, v, ww[p]);           // + |q|^2 for the col side
                UNPK2(ul, uh, u);
                c = fminf(c, fminf(ul, uh));
            }
            scolw[wid][idx] = fminf(scolw[wid][idx], c);
            idx = (idx == g + 31) ? g : idx + 1;
        }
    }

    // ---- row outputs: add deferred |q|^2, clamp, exact atomic min ----
    #pragma unroll
    for (int p = 0; p < 8; p++) {
        float we, wo;
        UNPK2(we, wo, ww[p]);
        float re = fmaxf(we + mn[2 * p],     0.0f);
        float ro = fmaxf(wo + mn[2 * p + 1], 0.0f);
        atomicMin(&g_minrowU[qbase + (2 * p) * THREADS + tid], __float_as_uint(re));
        atomicMin(&g_minrowU[qbase + (2 * p + 1) * THREADS + tid], __float_as_uint(ro));
    }

    __syncthreads();

    // ---- col outputs: merge 8 warp rows, clamp, exact atomic min ----
    if (tid < nt) {
        float m = fminf(fminf(fminf(scolw[0][tid], scolw[1][tid]),
                              fminf(scolw[2][tid], scolw[3][tid])),
                        fminf(fminf(scolw[4][tid], scolw[5][tid]),
                              fminf(scolw[6][tid], scolw[7][tid])));
        atomicMin(&g_mincolU[t0 + tid], __float_as_uint(fmaxf(m, 0.0f)));
    }
}

// ---------------------------------------------------------------------------
// Sum the 32768 clamped mins; last-done block finalizes deterministically.
// ---------------------------------------------------------------------------
__global__ void chamfer_combine_kernel(float* __restrict__ out) {
    __shared__ float red[8];
    int idx = blockIdx.x * 256 + threadIdx.x;     // 0..32767

    unsigned bits = (idx < NPTS) ? g_minrowU[idx] : g_mincolU[idx - NPTS];
    float r = __uint_as_float(bits);

    #pragma unroll
    for (int off = 16; off > 0; off >>= 1)
        r += __shfl_xor_sync(0xFFFFFFFFu, r, off);

    int lane = threadIdx.x & 31, warp = threadIdx.x >> 5;
    if (lane == 0) red[warp] = r;
    __syncthreads();
    if (threadIdx.x == 0) {
        float s = red[0];
        #pragma unroll
        for (int w = 1; w < 8; w++) s += red[w];
        g_partial[blockIdx.x] = s;
        __threadfence();
        unsigned done = atomicAdd(&g_count, 1u);
        if (done == 127u) {
            float tot = 0.0f;
            #pragma unroll
            for (int b = 0; b < 128; b++) tot += g_partial[b];
            out[0] = tot * (1.0f / (float)NPTS);
            g_count = 0;    // reset for next graph replay
        }
    }
}

// ---------------------------------------------------------------------------
extern "C" void kernel_launch(void* const* d_in, const int* in_sizes, int n_in,
                              void* d_out, int out_size) {
    const float* xc = (const float*)d_in[0];
    const float* xt = (const float*)d_in[1];
    float* out = (float*)d_out;

    chamfer_init_kernel<<<32, 512>>>();
    chamfer_fused_kernel<<<QC * TSLICES, THREADS>>>(xc, xt);
    chamfer_combine_kernel<<<128, 256>>>(out);
}

// round 13
// speedup vs baseline: 1.5143x; 1.5143x over previous
#include <cuda_runtime.h>
#include <cuda_bf16.h>
#include <cstdint>

#define NPTS    16384
#define THREADS 256
#define QPT     8                       // queries per thread (4 packed f32x2 pairs)
#define QPB     (THREADS * QPT)         // 2048 queries per block
#define QC      (NPTS / QPB)            // 8 query chunks
#define TSLICES 37                      // 8 * 37 = 296 blocks = 2 per SM
#define TS_MAX  443                     // ceil(16384 / 37)
#define TS_PAD  448                     // 14 groups of 32

// ---- device scratch (no allocations allowed) ----
__device__ unsigned g_minrowU[NPTS];    // float bits, clamped >=0, exact-min
__device__ unsigned g_mincolU[NPTS];
__device__ float    g_partial[128];
__device__ unsigned g_count = 0;

#define FMA2(d, a, b, c) \
    asm("fma.rn.f32x2 %0, %1, %2, %3;" : "=l"(d) : "l"(a), "l"(b), "l"(c))
#define ADD2(d, a, b) \
    asm("add.rn.f32x2 %0, %1, %2;" : "=l"(d) : "l"(a), "l"(b))
#define PACK2(d, lo, hi) \
    asm("mov.b64 %0, {%1, %2};" : "=l"(d) : "f"(lo), "f"(hi))
#define UNPK2(lo, hi, s) \
    asm("mov.b64 {%0, %1}, %2;" : "=f"(lo), "=f"(hi) : "l"(s))

// ---------------------------------------------------------------------------
__global__ void chamfer_init_kernel() {
    int i = blockIdx.x * blockDim.x + threadIdx.x;
    if (i < NPTS) { g_minrowU[i] = 0x7F800000u; g_mincolU[i] = 0x7F800000u; }
}

// ---------------------------------------------------------------------------
// Fused single-pass, rotation scheme, genuinely 2 CTAs/SM (QPT=8, ~80 regs).
// d2 = (|t|^2 + |q|^2) + a*x + b*y + c*z  computed fully per pair (round-10 form).
// Row mins: registers; col mins: per-warp smem rows; outputs via exact atomicMin.
// ---------------------------------------------------------------------------
__global__ __launch_bounds__(THREADS, 2) void chamfer_fused_kernel(
        const float* __restrict__ Xc, const float* __restrict__ Xt) {
    __shared__ float4 sA[TS_PAD];            // {x, x, y, y}
    __shared__ float4 sB[TS_PAD];            // {z, z, w, w}  (w = |t|^2)
    __shared__ float  scolw[8][TS_PAD];      // per-warp col-min accumulators

    const int bid = blockIdx.x;
    const int qc  = bid / TSLICES;           // 0..7
    const int ts  = bid % TSLICES;           // 0..36
    const int qbase = qc * QPB;
    const int t0  = ts * TS_MAX;
    const int nt  = min(TS_MAX, NPTS - t0);
    const int tid = threadIdx.x;
    const int wid = tid >> 5;
    const int lane = tid & 31;

    // ---- stage targets (sentinel-pad to 448) + init col accumulators ----
    #pragma unroll
    for (int k = 0; k < 2; k++) {
        int idx = tid + k * THREADS;
        if (idx < TS_PAD) {
            float x = 0.0f, y = 0.0f, z = 0.0f, w = 1e30f;
            if (idx < nt) {
                int gi = t0 + idx;
                x = Xt[3 * gi + 0]; y = Xt[3 * gi + 1]; z = Xt[3 * gi + 2];
                w = fmaf(x, x, fmaf(y, y, z * z));
            }
            sA[idx] = make_float4(x, x, y, y);
            sB[idx] = make_float4(z, z, w, w);
        }
    }
    #pragma unroll
    for (int k = 0; k < (8 * TS_PAD) / THREADS; k++)
        (&scolw[0][0])[tid + k * THREADS] = 3.4e38f;

    // ---- 8 queries per thread -> 4 packed coefficient quads (~32 regs) ----
    unsigned long long aa[4], bb[4], cc[4], ww[4];
    #pragma unroll
    for (int p = 0; p < 4; p++) {
        int qe = qbase + (2 * p) * THREADS + tid;
        int qo = qe + THREADS;
        float xe = Xc[3 * qe], ye = Xc[3 * qe + 1], ze = Xc[3 * qe + 2];
        float xo = Xc[3 * qo], yo = Xc[3 * qo + 1], zo = Xc[3 * qo + 2];
        PACK2(aa[p], -2.0f * xe, -2.0f * xo);
        PACK2(bb[p], -2.0f * ye, -2.0f * yo);
        PACK2(cc[p], -2.0f * ze, -2.0f * zo);
        PACK2(ww[p], fmaf(xe, xe, fmaf(ye, ye, ze * ze)),
                     fmaf(xo, xo, fmaf(yo, yo, zo * zo)));
    }

    float mn[8];
    #pragma unroll
    for (int q = 0; q < 8; q++) mn[q] = 3.4e38f;

    __syncthreads();

    // ---- main loop: 14 groups of 32 targets, rotated across lanes ----
    for (int g = 0; g < TS_PAD; g += 32) {
        int idx = g + lane;
        #pragma unroll 4
        for (int t = 0; t < 32; t++) {
            const ulonglong2 A = *reinterpret_cast<const ulonglong2*>(&sA[idx]);
            const ulonglong2 B = *reinterpret_cast<const ulonglong2*>(&sB[idx]);
            float d[8];
            #pragma unroll
            for (int p = 0; p < 4; p++) {
                unsigned long long s, v;
                ADD2(s, B.y, ww[p]);        // |t|^2 + |q|^2 (packed)
                FMA2(v, cc[p], B.x, s);     // + c*z
                FMA2(v, bb[p], A.y, v);     // + b*y
                FMA2(v, aa[p], A.x, v);     // + a*x  -> full d^2 (x2)
                UNPK2(d[2 * p], d[2 * p + 1], v);
                mn[2 * p]     = fminf(mn[2 * p],     d[2 * p]);
                mn[2 * p + 1] = fminf(mn[2 * p + 1], d[2 * p + 1]);
            }
            // col contribution: balanced tree over this thread's 8 queries
            float c = fminf(fminf(fminf(d[0], d[1]), fminf(d[2], d[3])),
                            fminf(fminf(d[4], d[5]), fminf(d[6], d[7])));
            scolw[wid][idx] = fminf(scolw[wid][idx], c);
            idx = (idx == g + 31) ? g : idx + 1;    // rotate within group
        }
    }

    // ---- row outputs: clamp, exact atomic min ----
    #pragma unroll
    for (int q = 0; q < 8; q++) {
        float r = fmaxf(mn[q], 0.0f);
        atomicMin(&g_minrowU[qbase + q * THREADS + tid], __float_as_uint(r));
    }

    __syncthreads();

    // ---- col outputs: merge 8 warp rows, clamp, exact atomic min ----
    for (int j = tid; j < nt; j += THREADS) {
        float m = fminf(fminf(fminf(scolw[0][j], scolw[1][j]),
                              fminf(scolw[2][j], scolw[3][j])),
                        fminf(fminf(scolw[4][j], scolw[5][j]),
                              fminf(scolw[6][j], scolw[7][j])));
        atomicMin(&g_mincolU[t0 + j], __float_as_uint(fmaxf(m, 0.0f)));
    }
}

// ---------------------------------------------------------------------------
// Sum the 32768 clamped mins; last-done block finalizes deterministically.
// ---------------------------------------------------------------------------
__global__ void chamfer_combine_kernel(float* __restrict__ out) {
    __shared__ float red[8];
    int idx = blockIdx.x * 256 + threadIdx.x;     // 0..32767

    unsigned bits = (idx < NPTS) ? g_minrowU[idx] : g_mincolU[idx - NPTS];
    float r = __uint_as_float(bits);

    #pragma unroll
    for (int off = 16; off > 0; off >>= 1)
        r += __shfl_xor_sync(0xFFFFFFFFu, r, off);

    int lane = threadIdx.x & 31, warp = threadIdx.x >> 5;
    if (lane == 0) red[warp] = r;
    __syncthreads();
    if (threadIdx.x == 0) {
        float s = red[0];
        #pragma unroll
        for (int w = 1; w < 8; w++) s += red[w];
        g_partial[blockIdx.x] = s;
        __threadfence();
        unsigned done = atomicAdd(&g_count, 1u);
        if (done == 127u) {
            float tot = 0.0f;
            #pragma unroll
            for (int b = 0; b < 128; b++) tot += g_partial[b];
            out[0] = tot * (1.0f / (float)NPTS);
            g_count = 0;    // reset for next graph replay
        }
    }
}

// ---------------------------------------------------------------------------
extern "C" void kernel_launch(void* const* d_in, const int* in_sizes, int n_in,
                              void* d_out, int out_size) {
    const float* xc = (const float*)d_in[0];
    const float* xt = (const float*)d_in[1];
    float* out = (float*)d_out;

    chamfer_init_kernel<<<32, 512>>>();
    chamfer_fused_kernel<<<QC * TSLICES, THREADS>>>(xc, xt);
    chamfer_combine_kernel<<<128, 256>>>(out);
}

// round 15
// speedup vs baseline: 1.6714x; 1.1037x over previous
#include <cuda_runtime.h>
#include <cuda_bf16.h>
#include <cstdint>

#define NPTS    16384
#define THREADS 512
#define QPT     16                      // queries per thread (8 packed f32x2 pairs)
#define QPB     (THREADS * QPT)         // 8192 queries per block
#define QC      (NPTS / QPB)            // 2 query chunks
#define TSLICES 74                      // 2 * 74 = 148 blocks = 1 per SM
#define TS_MAX  222                     // ceil(16384 / 74)
#define TS_PAD  224                     // 7 groups of 32
#define NWARPS  (THREADS / 32)          // 16

// ---- device scratch (no allocations allowed) ----
__device__ unsigned g_minrowU[NPTS];    // float bits, clamped >=0, exact-min
__device__ unsigned g_mincolU[NPTS];
__device__ float    g_partial[128];
__device__ unsigned g_count = 0;

#define FMA2(d, a, b, c) \
    asm("fma.rn.f32x2 %0, %1, %2, %3;" : "=l"(d) : "l"(a), "l"(b), "l"(c))
#define ADD2(d, a, b) \
    asm("add.rn.f32x2 %0, %1, %2;" : "=l"(d) : "l"(a), "l"(b))
#define PACK2(d, lo, hi) \
    asm("mov.b64 %0, {%1, %2};" : "=l"(d) : "f"(lo), "f"(hi))
#define UNPK2(lo, hi, s) \
    asm("mov.b64 {%0, %1}, %2;" : "=f"(lo), "=f"(hi) : "l"(s))

// ---------------------------------------------------------------------------
__global__ void chamfer_init_kernel() {
    int i = blockIdx.x * blockDim.x + threadIdx.x;
    if (i < NPTS) { g_minrowU[i] = 0x7F800000u; g_mincolU[i] = 0x7F800000u; }
}

// ---------------------------------------------------------------------------
// Fused single-pass, rotation scheme. 512 threads, 1 CTA/SM -> 4 warps/SMSP
// with a full 128-reg/thread budget (no 2-CTA cap, no spills).
// d2 = (|t|^2 + |q|^2) + a*x + b*y + c*z  (round-10 proven form).
// Row mins: registers; col mins: per-warp smem rows; outputs: exact atomicMin.
// ---------------------------------------------------------------------------
__global__ __launch_bounds__(THREADS, 1) void chamfer_fused_kernel(
        const float* __restrict__ Xc, const float* __restrict__ Xt) {
    __shared__ float4 sA[TS_PAD];                // {x, x, y, y}
    __shared__ float4 sB[TS_PAD];                // {z, z, w, w}  (w = |t|^2)
    __shared__ float  scolw[NWARPS][TS_PAD];     // per-warp col-min accumulators

    const int bid = blockIdx.x;
    const int qc  = bid / TSLICES;           // 0..1
    const int ts  = bid % TSLICES;           // 0..73
    const int qbase = qc * QPB;
    const int t0  = ts * TS_MAX;
    const int nt  = min(TS_MAX, NPTS - t0);
    const int tid = threadIdx.x;
    const int wid = tid >> 5;
    const int lane = tid & 31;

    // ---- stage targets (sentinel-pad to 224) + init col accumulators ----
    if (tid < TS_PAD) {
        float x = 0.0f, y = 0.0f, z = 0.0f, w = 1e30f;
        if (tid < nt) {
            int gi = t0 + tid;
            x = Xt[3 * gi + 0]; y = Xt[3 * gi + 1]; z = Xt[3 * gi + 2];
            w = fmaf(x, x, fmaf(y, y, z * z));
        }
        sA[tid] = make_float4(x, x, y, y);
        sB[tid] = make_float4(z, z, w, w);
    }
    #pragma unroll
    for (int k = 0; k < (NWARPS * TS_PAD) / THREADS; k++)
        (&scolw[0][0])[tid + k * THREADS] = 3.4e38f;

    // ---- 16 queries per thread -> 8 packed coefficient quads ----
    unsigned long long aa[8], bb[8], cc[8], ww[8];
    #pragma unroll
    for (int p = 0; p < 8; p++) {
        int qe = qbase + (2 * p) * THREADS + tid;
        int qo = qe + THREADS;
        float xe = Xc[3 * qe], ye = Xc[3 * qe + 1], ze = Xc[3 * qe + 2];
        float xo = Xc[3 * qo], yo = Xc[3 * qo + 1], zo = Xc[3 * qo + 2];
        PACK2(aa[p], -2.0f * xe, -2.0f * xo);
        PACK2(bb[p], -2.0f * ye, -2.0f * yo);
        PACK2(cc[p], -2.0f * ze, -2.0f * zo);
        PACK2(ww[p], fmaf(xe, xe, fmaf(ye, ye, ze * ze)),
                     fmaf(xo, xo, fmaf(yo, yo, zo * zo)));
    }

    float mn[16];
    #pragma unroll
    for (int q = 0; q < 16; q++) mn[q] = 3.4e38f;

    __syncthreads();

    // ---- main loop: 7 groups of 32 targets, rotated across lanes ----
    for (int g = 0; g < TS_PAD; g += 32) {
        int idx = g + lane;
        #pragma unroll 2
        for (int t = 0; t < 32; t++) {
            const ulonglong2 A = *reinterpret_cast<const ulonglong2*>(&sA[idx]);
            const ulonglong2 B = *reinterpret_cast<const ulonglong2*>(&sB[idx]);
            float d[16];
            #pragma unroll
            for (int p = 0; p < 8; p++) {
                unsigned long long s, v;
                ADD2(s, B.y, ww[p]);        // |t|^2 + |q|^2 (packed)
                FMA2(v, cc[p], B.x, s);     // + c*z
                FMA2(v, bb[p], A.y, v);     // + b*y
                FMA2(v, aa[p], A.x, v);     // + a*x  -> full d^2 (x2)
                UNPK2(d[2 * p], d[2 * p + 1], v);
                mn[2 * p]     = fminf(mn[2 * p],     d[2 * p]);
                mn[2 * p + 1] = fminf(mn[2 * p + 1], d[2 * p + 1]);
            }
            // col contribution: balanced tree over this thread's 16 queries
            float c = fminf(
                fminf(fminf(fminf(d[0], d[1]),   fminf(d[2], d[3])),
                      fminf(fminf(d[4], d[5]),   fminf(d[6], d[7]))),
                fminf(fminf(fminf(d[8], d[9]),   fminf(d[10], d[11])),
                      fminf(fminf(d[12], d[13]), fminf(d[14], d[15]))));
            scolw[wid][idx] = fminf(scolw[wid][idx], c);
            idx = (idx == g + 31) ? g : idx + 1;    // rotate within group
        }
    }

    // ---- row outputs: clamp, exact atomic min ----
    #pragma unroll
    for (int q = 0; q < 16; q++) {
        float r = fmaxf(mn[q], 0.0f);
        atomicMin(&g_minrowU[qbase + q * THREADS + tid], __float_as_uint(r));
    }

    __syncthreads();

    // ---- col outputs: merge 16 warp rows, clamp, exact atomic min ----
    if (tid < nt) {
        float m = 3.4e38f;
        #pragma unroll
        for (int w = 0; w < NWARPS; w++)
            m = fminf(m, scolw[w][tid]);
        atomicMin(&g_mincolU[t0 + tid], __float_as_uint(fmaxf(m, 0.0f)));
    }
}

// ---------------------------------------------------------------------------
// Sum the 32768 clamped mins; last-done block finalizes deterministically.
// ---------------------------------------------------------------------------
__global__ void chamfer_combine_kernel(float* __restrict__ out) {
    __shared__ float red[8];
    int idx = blockIdx.x * 256 + threadIdx.x;     // 0..32767

    unsigned bits = (idx < NPTS) ? g_minrowU[idx] : g_mincolU[idx - NPTS];
    float r = __uint_as_float(bits);

    #pragma unroll
    for (int off = 16; off > 0; off >>= 1)
        r += __shfl_xor_sync(0xFFFFFFFFu, r, off);

    int lane = threadIdx.x & 31, warp = threadIdx.x >> 5;
    if (lane == 0) red[warp] = r;
    __syncthreads();
    if (threadIdx.x == 0) {
        float s = red[0];
        #pragma unroll
        for (int w = 1; w < 8; w++) s += red[w];
        g_partial[blockIdx.x] = s;
        __threadfence();
        unsigned done = atomicAdd(&g_count, 1u);
        if (done == 127u) {
            float tot = 0.0f;
            #pragma unroll
            for (int b = 0; b < 128; b++) tot += g_partial[b];
            out[0] = tot * (1.0f / (float)NPTS);
            g_count = 0;    // reset for next graph replay
        }
    }
}

// ---------------------------------------------------------------------------
extern "C" void kernel_launch(void* const* d_in, const int* in_sizes, int n_in,
                              void* d_out, int out_size) {
    const float* xc = (const float*)d_in[0];
    const float* xt = (const float*)d_in[1];
    float* out = (float*)d_out;

    chamfer_init_kernel<<<32, 512>>>();
    chamfer_fused_kernel<<<QC * TSLICES, THREADS>>>(xc, xt);
    chamfer_combine_kernel<<<128, 256>>>(out);
}